// round 11
// baseline (speedup 1.0000x reference)
#include <cuda_runtime.h>
#include <cstdint>

typedef unsigned long long u64;

// ---- packed f32x2 primitives (Blackwell FFMA2 path, PTX-only) ----
__device__ __forceinline__ u64 pk(float lo, float hi) {
    u64 r; asm("mov.b64 %0, {%1, %2};" : "=l"(r) : "f"(lo), "f"(hi)); return r;
}
__device__ __forceinline__ void upk(u64 v, float& lo, float& hi) {
    asm("mov.b64 {%0, %1}, %2;" : "=f"(lo), "=f"(hi) : "l"(v));
}
__device__ __forceinline__ u64 fma2(u64 a, u64 b, u64 c) {
    u64 d; asm("fma.rn.f32x2 %0, %1, %2, %3;" : "=l"(d) : "l"(a), "l"(b), "l"(c)); return d;
}
__device__ __forceinline__ u64 mul2(u64 a, u64 b) {
    u64 d; asm("mul.rn.f32x2 %0, %1, %2;" : "=l"(d) : "l"(a), "l"(b)); return d;
}
__device__ __forceinline__ u64 add2(u64 a, u64 b) {
    u64 d; asm("add.rn.f32x2 %0, %1, %2;" : "=l"(d) : "l"(a), "l"(b)); return d;
}

// smem constant table layout (float2, both lanes equal):
//  0..11 : observable coefficients with Z-parity signs folded in
//  12 INV2PI  13 MAGIC  14 -2pi_hi  15 -2pi_lo
//  16..21 sin c13,c11,c9,c7,c5,c3   22..28 cos d14..d2   29 ONE  30 NEG1  31 -MAGIC
#define SC(i) (*(const u64*)(scp + (i)))

// Packed polynomial sincos: |t| reduced by one 2pi period (inputs ~N(0,1)).
__device__ __forceinline__ void poly_sc(u64 t, const float2* scp, u64& s, u64& c) {
    u64 u = mul2(t, SC(12));
    u64 k = add2(u, SC(13));      // round-to-nearest via magic number
    k = add2(k, SC(31));
    u64 r = fma2(k, SC(14), t);
    r = fma2(k, SC(15), r);
    u64 r2 = mul2(r, r);
    u64 p = SC(16);
    p = fma2(r2, p, SC(17));
    p = fma2(r2, p, SC(18));
    p = fma2(r2, p, SC(19));
    p = fma2(r2, p, SC(20));
    p = fma2(r2, p, SC(21));
    s = mul2(r, fma2(r2, p, SC(29)));
    u64 q = SC(22);
    q = fma2(r2, q, SC(23));
    q = fma2(r2, q, SC(24));
    q = fma2(r2, q, SC(25));
    q = fma2(r2, q, SC(26));
    q = fma2(r2, q, SC(27));
    q = fma2(r2, q, SC(28));
    c = fma2(r2, q, SC(29));
}

__global__ __launch_bounds__(256, 2) void vqc_pk(const float4* __restrict__ enc,
                                                 const float* __restrict__ w,
                                                 float4* __restrict__ out,
                                                 int B) {
    __shared__ __align__(8) float2 sc[32];
    const int tid = threadIdx.x;

    if (tid < 4) {
        int q = tid;
        float st, ct, sl, cl;
        __sincosf(w[q * 3 + 0], &st, &ct);
        __sincosf(w[q * 3 + 2], &sl, &cl);
        float nx = -st * cl, ny = st * sl, nz = ct;
        // fold z = -Z parity signs into coefficients
        const float syq[4] = {1.f, -1.f, 1.f, 1.f};
        const float szq[4] = {-1.f, 1.f, -1.f, 1.f};
        float a = nx, b = syq[q] * ny, d = szq[q] * nz;
        sc[q * 3 + 0] = make_float2(a, a);
        sc[q * 3 + 1] = make_float2(b, b);
        sc[q * 3 + 2] = make_float2(d, d);
    }
    if (tid == 0) {
        const float k[20] = {
            0.15915494309189535f, 12582912.0f, -6.28125f, -1.9353071795864769e-3f,
            1.60590438e-10f, -2.50521084e-8f, 2.75573192e-6f, -1.98412698e-4f,
            8.33333333e-3f, -1.66666667e-1f,
            -1.14707456e-11f, 2.08767570e-9f, -2.75573192e-7f, 2.48015873e-5f,
            -1.38888889e-3f, 4.16666667e-2f, -0.5f,
            1.0f, -1.0f, -12582912.0f};
        for (int i = 0; i < 20; i++) sc[12 + i] = make_float2(k[i], k[i]);
    }
    __syncthreads();
    const float2* scp = sc;

    const int pairs = (B + 1) >> 1;
    const int g = blockIdx.x * 256 + tid;
    if (g >= pairs) return;

    const int i0 = 2 * g;
    const bool has2 = (i0 + 1 < B);
    const float4* p = enc + 3 * i0;
    float4 a0 = __ldcs(p + 0), a1 = __ldcs(p + 1), a2 = __ldcs(p + 2);
    float4 b0 = a0, b1 = a1, b2 = a2;
    if (has2) { b0 = __ldcs(p + 3); b1 = __ldcs(p + 4); b2 = __ldcs(p + 5); }

    const float tA[12] = {a0.x, a0.y, a0.z, a0.w, a1.x, a1.y, a1.z, a1.w,
                          a2.x, a2.y, a2.z, a2.w};
    const float tB[12] = {b0.x, b0.y, b0.z, b0.w, b1.x, b1.y, b1.z, b1.w,
                          b2.x, b2.y, b2.z, b2.w};

    u64 X[4], Y[4], Z[4];
    const u64 NEG1 = SC(30);
#pragma unroll
    for (int q = 0; q < 4; q++) {
        // t0,t1 on MUFU (scalar), t2 on packed FMA polynomial
        float s0A, c0A, s1A, c1A, s0B, c0B, s1B, c1B;
        __sincosf(tA[3 * q + 0], &s0A, &c0A);
        __sincosf(tA[3 * q + 1], &s1A, &c1A);
        __sincosf(tB[3 * q + 0], &s0B, &c0B);
        __sincosf(tB[3 * q + 1], &s1B, &c1B);
        u64 c0 = pk(c0A, c0B), c1 = pk(c1A, c1B);
        u64 s0 = pk(s0A, s0B), s1 = pk(s1A, s1B);
        u64 s2, c2;
        poly_sc(pk(tA[3 * q + 2], tB[3 * q + 2]), scp, s2, c2);

        u64 cc = mul2(c0, c1);
        Z[q] = mul2(c0, s1);                    // Z = c0*s1 (= -z; signs in coeffs)
        u64 s0n = mul2(s0, NEG1);
        X[q] = fma2(s2, s0n, mul2(c2, cc));     // x = c2*cc - s2*s0
        Y[q] = fma2(c2, s0, mul2(s2, cc));      // y = s2*cc + c2*s0
    }

    u64 Z01 = mul2(Z[0], Z[1]);
    u64 Z23 = mul2(Z[2], Z[3]);
    u64 Z123 = mul2(Z[1], Z23);
    u64 Z012 = mul2(Z01, Z[2]);
    u64 Z0123 = mul2(Z01, Z23);
    u64 x01 = mul2(X[0], X[1]);

    u64 t0 = mul2(mul2(X[0], Y[1]), Z23);
    u64 ox = fma2(t0, SC(1), fma2(x01, SC(0), mul2(Z123, SC(2))));

    u64 t1 = mul2(mul2(Z[0], Y[1]), X[2]);
    u64 oy = fma2(t1, SC(4), fma2(mul2(X[1], X[2]), SC(3), mul2(Z01, SC(5))));

    u64 t2 = mul2(mul2(Z01, Y[2]), X[3]);
    u64 oz = fma2(t2, SC(7), fma2(mul2(X[2], X[3]), SC(6), mul2(Z012, SC(8))));

    u64 t3 = mul2(mul2(mul2(Y[0], Y[1]), Z[2]), Y[3]);
    u64 ow = fma2(t3, SC(10), fma2(mul2(x01, X[3]), SC(9), mul2(Z0123, SC(11))));

    float4 oA, oB;
    upk(ox, oA.x, oB.x);
    upk(oy, oA.y, oB.y);
    upk(oz, oA.z, oB.z);
    upk(ow, oA.w, oB.w);
    __stcs(&out[i0], oA);
    if (has2) __stcs(&out[i0 + 1], oB);
}

extern "C" void kernel_launch(void* const* d_in, const int* in_sizes, int n_in,
                              void* d_out, int out_size) {
    int ei = 0, wi = 1;
    if (n_in >= 2 && in_sizes[0] < in_sizes[1]) { ei = 1; wi = 0; }
    const float* enc = (const float*)d_in[ei];
    const float* w   = (const float*)d_in[wi];
    int B = in_sizes[ei] / 12;

    int pairs = (B + 1) / 2;
    int blocks = (pairs + 255) / 256;
    vqc_pk<<<blocks, 256>>>((const float4*)enc, w, (float4*)d_out, B);
}

// round 12
// speedup vs baseline: 1.2176x; 1.2176x over previous
#include <cuda_runtime.h>

__device__ __forceinline__ float4 vqc_one(float4 e0, float4 e1, float4 e2,
                                          float4 n0, float4 n1, float4 n2) {
    float t[12] = {e0.x, e0.y, e0.z, e0.w,
                   e1.x, e1.y, e1.z, e1.w,
                   e2.x, e2.y, e2.z, e2.w};
    float x[4], y[4], z[4];
#pragma unroll
    for (int q = 0; q < 4; q++) {
        float s0, c0, s1, c1, s2, c2;
        __sincosf(t[3 * q + 0], &s0, &c0);
        __sincosf(t[3 * q + 1], &s1, &c1);
        __sincosf(t[3 * q + 2], &s2, &c2);
        float cc = c0 * c1;
        float ss = s0 * s2;
        float sc = s0 * c2;
        x[q] = __fmaf_rn(c2, cc, -ss);
        y[q] = __fmaf_rn(s2, cc, sc);
        z[q] = -c0 * s1;
    }
    float z01   = z[0] * z[1];
    float z23   = z[2] * z[3];
    float z012  = z01 * z[2];
    float z123  = z[1] * z23;
    float z0123 = z01 * z23;
    float x01   = x[0] * x[1];

    float4 o;
    o.x = __fmaf_rn(n0.x, x01, __fmaf_rn(n0.y, x[0] * y[1] * z23, n0.z * z123));
    o.y = __fmaf_rn(n0.w, x[1] * x[2], __fmaf_rn(n1.x, z[0] * y[1] * x[2], n1.y * z01));
    o.z = __fmaf_rn(n1.z, x[2] * x[3], __fmaf_rn(n1.w, z01 * y[2] * x[3], n2.x * z012));
    o.w = __fmaf_rn(n2.y, x01 * x[3],
                    __fmaf_rn(-n2.z, y[0] * y[1] * z[2] * y[3], n2.w * z0123));
    return o;
}

// 8 blocks/SM (32-reg class) x 152 SMs = 1216 blocks: one full-occupancy wave.
__global__ __launch_bounds__(256, 8) void vqc_fused(const float4* __restrict__ enc,
                                                    const float* __restrict__ w,
                                                    float4* __restrict__ out,
                                                    int B) {
    __shared__ __align__(16) float sn[12];
    if (threadIdx.x < 4) {
        int q = threadIdx.x;
        float st, ct, sl, cl;
        __sincosf(w[q * 3 + 0], &st, &ct);
        __sincosf(w[q * 3 + 2], &sl, &cl);
        sn[q * 3 + 0] = -st * cl;
        sn[q * 3 + 1] =  st * sl;
        sn[q * 3 + 2] =  ct;
    }
    __syncthreads();
    const float4* n4 = (const float4*)sn;
    const float4 n0 = n4[0], n1 = n4[1], n2 = n4[2];

    const int stride = gridDim.x * blockDim.x;
    int i = blockIdx.x * blockDim.x + threadIdx.x;
    const float4* p = enc + 3 * i;
    const long pstep = 3 * (long)stride;

#pragma unroll 1
    for (; i < B; i += stride, p += pstep) {
        float4 e0 = p[0];
        float4 e1 = p[1];
        float4 e2 = p[2];
        float4 o = vqc_one(e0, e1, e2, n0, n1, n2);
        out[i] = o;
    }
}

extern "C" void kernel_launch(void* const* d_in, const int* in_sizes, int n_in,
                              void* d_out, int out_size) {
    int ei = 0, wi = 1;
    if (n_in >= 2 && in_sizes[0] < in_sizes[1]) { ei = 1; wi = 0; }
    const float* enc = (const float*)d_in[ei];
    const float* w   = (const float*)d_in[wi];
    int B = in_sizes[ei] / 12;

    const int threads = 256;
    const int max_blocks = 152 * 8;   // one resident wave at full occupancy
    int need = (B + threads - 1) / threads;
    int blocks = need < max_blocks ? need : max_blocks;

    vqc_fused<<<blocks, threads>>>((const float4*)enc, w, (float4*)d_out, B);
}

// round 13
// speedup vs baseline: 1.3183x; 1.0827x over previous
#include <cuda_runtime.h>

__device__ __forceinline__ float4 vqc_one(float4 e0, float4 e1, float4 e2,
                                          float4 n0, float4 n1, float4 n2) {
    float t[12] = {e0.x, e0.y, e0.z, e0.w,
                   e1.x, e1.y, e1.z, e1.w,
                   e2.x, e2.y, e2.z, e2.w};
    float x[4], y[4], z[4];
#pragma unroll
    for (int q = 0; q < 4; q++) {
        float s0, c0, s1, c1, s2, c2;
        __sincosf(t[3 * q + 0], &s0, &c0);
        __sincosf(t[3 * q + 1], &s1, &c1);
        __sincosf(t[3 * q + 2], &s2, &c2);
        float cc = c0 * c1;
        x[q] = cc * c2 - s0 * s2;
        y[q] = cc * s2 + s0 * c2;
        z[q] = -c0 * s1;
    }
    float z01   = z[0] * z[1];
    float z23   = z[2] * z[3];
    float z012  = z01 * z[2];
    float z123  = z[1] * z23;
    float z0123 = z01 * z23;
    float x01   = x[0] * x[1];

    // All string signs folded into the precomputed coefficients.
    float4 o;
    o.x = n0.x * x01           + n0.y * (x[0] * y[1] * z23)         + n0.z * z123;
    o.y = n0.w * (x[1] * x[2]) + n1.x * (z[0] * y[1] * x[2])        + n1.y * z01;
    o.z = n1.z * (x[2] * x[3]) + n1.w * (z01 * y[2] * x[3])         + n2.x * z012;
    o.w = n2.y * (x01 * x[3])  + n2.z * (y[0] * y[1] * z[2] * y[3]) + n2.w * z0123;
    return o;
}

__global__ __launch_bounds__(256) void vqc_fused(const float4* __restrict__ enc,
                                                 const float* __restrict__ w,
                                                 float4* __restrict__ out,
                                                 int B) {
    __shared__ __align__(16) float sn[12];
    if (threadIdx.x < 4) {
        int q = threadIdx.x;
        float st, ct, sl, cl;
        __sincosf(w[q * 3 + 0], &st, &ct);
        __sincosf(w[q * 3 + 2], &sl, &cl);
        sn[q * 3 + 0] = -st * cl;                     // nx
        sn[q * 3 + 1] = (q == 3) ? -st * sl : st * sl; // ny (minus of Y-string on q3 folded)
        sn[q * 3 + 2] =  ct;                          // nz
    }
    __syncthreads();
    const float4* n4 = (const float4*)sn;
    const float4 n0 = n4[0], n1 = n4[1], n2 = n4[2];

    const int stride = gridDim.x * blockDim.x;
    int i = blockIdx.x * blockDim.x + threadIdx.x;

    for (; i < B; i += stride) {
        const float4* p = enc + 3 * i;
        float4 e0 = p[0];
        float4 e1 = p[1];
        float4 e2 = p[2];
        float4 o = vqc_one(e0, e1, e2, n0, n1, n2);
        out[i] = o;
    }
}

extern "C" void kernel_launch(void* const* d_in, const int* in_sizes, int n_in,
                              void* d_out, int out_size) {
    int ei = 0, wi = 1;
    if (n_in >= 2 && in_sizes[0] < in_sizes[1]) { ei = 1; wi = 0; }
    const float* enc = (const float*)d_in[ei];
    const float* w   = (const float*)d_in[wi];
    int B = in_sizes[ei] / 12;

    const int threads = 256;
    int max_blocks = 152 * 8;   // persistent grid; occupancy-capped by reg class
    int need = (B + threads - 1) / threads;
    int blocks = need < max_blocks ? need : max_blocks;

    vqc_fused<<<blocks, threads>>>((const float4*)enc, w, (float4*)d_out, B);
}